// round 14
// baseline (speedup 1.0000x reference)
#include <cuda_runtime.h>
#include <cuda_bf16.h>
#include <cooperative_groups.h>
#include <cstdint>

namespace cg = cooperative_groups;

#define N_NODES 100000
#define F 128
#define MAXE 1600000

#define COOP_G 592            // 4 blocks/SM x 148 SMs, all co-resident
#define COOP_T 256
#define CHUNK_C ((N_NODES + COOP_G - 1) / COOP_G)   // 169 (<= 256)

#define TILE_M 32
#define NT2 (N_NODES / TILE_M)                      // 3125 exact
#define LDAB 528
#define ABUF_LO 16896
#define ABUF_SZ 33792
#define OFF_BHI (2 * ABUF_SZ)
#define OFF_BLO (OFF_BHI + 128 * LDAB)
#define SMEM_T  (OFF_BLO + 128 * LDAB)              // 202752

// Scratch (allocation-free rule: __device__ globals)
__device__ int   g_cnt[N_NODES];
__device__ int   g_cur[N_NODES];
__device__ int   g_off[N_NODES];
__device__ int   g_bsum[COOP_G];
__device__ int   g_csr[MAXE];
__device__ uint2 g_agghi[N_NODES * 32];
__device__ uint2 g_agglo[N_NODES * 32];
__device__ uint2 g_xhi[N_NODES * 32];
__device__ uint2 g_xlo[N_NODES * 32];

// ---- bf16 rn split: hi = rn(v) (unbiased), lo = rn(v - float(hi)) ----
__device__ __forceinline__ uint32_t cvt2(float f0, float f1) {
    uint32_t d;
    asm("cvt.rn.bf16x2.f32 %0, %1, %2;" : "=r"(d) : "f"(f1), "f"(f0));
    return d;
}
__device__ __forceinline__ float4 bf4_to_f4(uint2 p) {
    float2 a = __bfloat1622float2(*(const __nv_bfloat162*)&p.x);
    float2 b = __bfloat1622float2(*(const __nv_bfloat162*)&p.y);
    return make_float4(a.x, a.y, b.x, b.y);
}
__device__ __forceinline__ void split4(float4 v, uint2& hi, uint2& lo) {
    hi.x = cvt2(v.x, v.y);
    hi.y = cvt2(v.z, v.w);
    float4 h = bf4_to_f4(hi);
    lo.x = cvt2(v.x - h.x, v.y - h.y);
    lo.y = cvt2(v.z - h.z, v.w - h.w);
}

#define MMA16816(c, a0, a1, a2, a3, b0, b1) \
    asm volatile("mma.sync.aligned.m16n8k16.row.col.f32.bf16.bf16.f32 " \
                 "{%0,%1,%2,%3}, {%4,%5,%6,%7}, {%8,%9}, {%0,%1,%2,%3};" \
                 : "+f"((c)[0]), "+f"((c)[1]), "+f"((c)[2]), "+f"((c)[3]) \
                 : "r"(a0), "r"(a1), "r"(a2), "r"(a3), "r"(b0), "r"(b1))
#define LDSM4(r0, r1, r2, r3, addr) \
    asm volatile("ldmatrix.sync.aligned.m8n8.x4.shared.b16 {%0,%1,%2,%3}, [%4];" \
                 : "=r"(r0), "=r"(r1), "=r"(r2), "=r"(r3) : "r"(addr))
#define LDSM2(r0, r1, addr) \
    asm volatile("ldmatrix.sync.aligned.m8n8.x2.shared.b16 {%0,%1}, [%2];" \
                 : "=r"(r0), "=r"(r1) : "r"(addr))
#define CP16(dst, src, ssz) \
    asm volatile("cp.async.cg.shared.global [%0], [%1], 16, %2;" \
                 :: "r"(dst), "l"(src), "r"(ssz) : "memory")
#define CP_COMMIT() asm volatile("cp.async.commit_group;" ::: "memory")
#define CP_WAIT1()  asm volatile("cp.async.wait_group 1;" ::: "memory")

__device__ __forceinline__ uint32_t smem_u32(const void* p) {
    uint32_t a;
    asm("{ .reg .u64 t; cvta.to.shared.u64 t, %1; cvt.u32.u64 %0, t; }"
        : "=r"(a) : "l"(p));
    return a;
}

// ============ cooperative preprocessing: zero | xconv+hist | scan | fill ====
__global__ void __launch_bounds__(COOP_T, 4)
prep_kernel(const int* __restrict__ ei, int E, const float* __restrict__ x) {
    cg::grid_group grid = cg::this_grid();
    __shared__ int s[COOP_T];
    int tid = threadIdx.x;
    int bid = blockIdx.x;
    int gid = bid * COOP_T + tid;
    int gstride = COOP_G * COOP_T;

    // ---- P0: zero counters ----
    for (int i = gid; i < N_NODES; i += gstride) g_cnt[i] = 0;
    grid.sync();

    // ---- P1: xconv (independent) + hist ----
    {
        uint4* xhi4 = (uint4*)(void*)g_xhi;
        uint4* xlo4 = (uint4*)(void*)g_xlo;
        for (int i = gid; i < N_NODES * 16; i += gstride) {
            float4 v0 = ((const float4*)x)[i * 2];
            float4 v1 = ((const float4*)x)[i * 2 + 1];
            uint2 h0, l0, h1, l1;
            split4(v0, h0, l0);
            split4(v1, h1, l1);
            xhi4[i] = make_uint4(h0.x, h0.y, h1.x, h1.y);
            xlo4[i] = make_uint4(l0.x, l0.y, l1.x, l1.y);
        }
        int E4 = E >> 2;
        const int4* d4 = (const int4*)(ei + E);
        for (int e = gid; e < E4; e += gstride) {
            int4 d = d4[e];
            if ((unsigned)d.x < (unsigned)N_NODES) atomicAdd(&g_cnt[d.x], 1);
            if ((unsigned)d.y < (unsigned)N_NODES) atomicAdd(&g_cnt[d.y], 1);
            if ((unsigned)d.z < (unsigned)N_NODES) atomicAdd(&g_cnt[d.z], 1);
            if ((unsigned)d.w < (unsigned)N_NODES) atomicAdd(&g_cnt[d.w], 1);
        }
        for (int e = (E4 << 2) + gid; e < E; e += gstride) {
            int d = ei[E + e];
            if ((unsigned)d < (unsigned)N_NODES) atomicAdd(&g_cnt[d], 1);
        }
    }
    grid.sync();

    // ---- P2: per-block exclusive scan of this block's CHUNK_C nodes ----
    int base0 = bid * CHUNK_C;
    int node = base0 + tid;
    int v = (tid < CHUNK_C && node < N_NODES) ? g_cnt[node] : 0;
    s[tid] = v;
    __syncthreads();
#pragma unroll
    for (int d = 1; d < COOP_T; d <<= 1) {
        int t = (tid >= d) ? s[tid - d] : 0;
        __syncthreads();
        s[tid] += t;
        __syncthreads();
    }
    int excl = s[tid] - v;               // local exclusive prefix
    if (tid == COOP_T - 1) g_bsum[bid] = s[tid];
    grid.sync();

    // ---- P3: add global base = sum bsum[0..bid), write off/cur ----
    {
        int sum = 0;
        for (int i = tid; i < bid; i += COOP_T) sum += g_bsum[i];
        __syncthreads();                  // s reuse safe
        s[tid] = sum;
        __syncthreads();
#pragma unroll
        for (int d = COOP_T / 2; d > 0; d >>= 1) {
            if (tid < d) s[tid] += s[tid + d];
            __syncthreads();
        }
        int base = s[0];
        if (tid < CHUNK_C && node < N_NODES) {
            int off = excl + base;
            g_off[node] = off;
            g_cur[node] = off;
        }
    }
    grid.sync();

    // ---- P4: CSR fill ----
    {
        int E4 = E >> 2;
        const int4* s4 = (const int4*)ei;
        const int4* d4 = (const int4*)(ei + E);
        for (int e = gid; e < E4; e += gstride) {
            int4 sv = s4[e];
            int4 dv = d4[e];
            if ((unsigned)sv.x < (unsigned)N_NODES && (unsigned)dv.x < (unsigned)N_NODES)
                g_csr[atomicAdd(&g_cur[dv.x], 1)] = sv.x;
            if ((unsigned)sv.y < (unsigned)N_NODES && (unsigned)dv.y < (unsigned)N_NODES)
                g_csr[atomicAdd(&g_cur[dv.y], 1)] = sv.y;
            if ((unsigned)sv.z < (unsigned)N_NODES && (unsigned)dv.z < (unsigned)N_NODES)
                g_csr[atomicAdd(&g_cur[dv.z], 1)] = sv.z;
            if ((unsigned)sv.w < (unsigned)N_NODES && (unsigned)dv.w < (unsigned)N_NODES)
                g_csr[atomicAdd(&g_cur[dv.w], 1)] = sv.w;
        }
        for (int e = (E4 << 2) + gid; e < E; e += gstride) {
            int sv = ei[e];
            int dv = ei[E + e];
            if ((unsigned)sv < (unsigned)N_NODES && (unsigned)dv < (unsigned)N_NODES)
                g_csr[atomicAdd(&g_cur[dv], 1)] = sv;
        }
    }
}

// ---- aggregate: warp per node; paired-lane bf16 gather (LDG.128) ----
__global__ void aggregate_kernel() {
    int gtid = blockIdx.x * blockDim.x + threadIdx.x;
    int w = gtid >> 5;
    int lane = gtid & 31;
    if (w >= N_NODES) return;
    int off = g_off[w];
    int deg = g_cnt[w];
    int end = off + deg;

    int h = lane >> 4;
    int hl = lane & 15;
    const uint4* xh4 = (const uint4*)(const void*)g_xhi;

    float4 accA0 = make_float4(0.f,0.f,0.f,0.f), accA1 = accA0;
    float4 accB0 = accA0, accB1 = accA0;

    int i = off;
    for (; i + 8 <= end; i += 8) {
        int e0 = g_csr[i + h];
        int e1 = g_csr[i + 2 + h];
        int e2 = g_csr[i + 4 + h];
        int e3 = g_csr[i + 6 + h];
        uint4 p0 = xh4[e0 * 16 + hl];
        uint4 p1 = xh4[e1 * 16 + hl];
        uint4 p2 = xh4[e2 * 16 + hl];
        uint4 p3 = xh4[e3 * 16 + hl];
        float4 v;
        v = bf4_to_f4(make_uint2(p0.x, p0.y));
        accA0.x += v.x; accA0.y += v.y; accA0.z += v.z; accA0.w += v.w;
        v = bf4_to_f4(make_uint2(p0.z, p0.w));
        accA1.x += v.x; accA1.y += v.y; accA1.z += v.z; accA1.w += v.w;
        v = bf4_to_f4(make_uint2(p1.x, p1.y));
        accB0.x += v.x; accB0.y += v.y; accB0.z += v.z; accB0.w += v.w;
        v = bf4_to_f4(make_uint2(p1.z, p1.w));
        accB1.x += v.x; accB1.y += v.y; accB1.z += v.z; accB1.w += v.w;
        v = bf4_to_f4(make_uint2(p2.x, p2.y));
        accA0.x += v.x; accA0.y += v.y; accA0.z += v.z; accA0.w += v.w;
        v = bf4_to_f4(make_uint2(p2.z, p2.w));
        accA1.x += v.x; accA1.y += v.y; accA1.z += v.z; accA1.w += v.w;
        v = bf4_to_f4(make_uint2(p3.x, p3.y));
        accB0.x += v.x; accB0.y += v.y; accB0.z += v.z; accB0.w += v.w;
        v = bf4_to_f4(make_uint2(p3.z, p3.w));
        accB1.x += v.x; accB1.y += v.y; accB1.z += v.z; accB1.w += v.w;
    }
    for (; i + 2 <= end; i += 2) {
        int e = g_csr[i + h];
        uint4 p = xh4[e * 16 + hl];
        float4 v = bf4_to_f4(make_uint2(p.x, p.y));
        accA0.x += v.x; accA0.y += v.y; accA0.z += v.z; accA0.w += v.w;
        v = bf4_to_f4(make_uint2(p.z, p.w));
        accA1.x += v.x; accA1.y += v.y; accA1.z += v.z; accA1.w += v.w;
    }
    if (i < end && h == 0) {
        int e = g_csr[i];
        uint4 p = xh4[e * 16 + hl];
        float4 v = bf4_to_f4(make_uint2(p.x, p.y));
        accA0.x += v.x; accA0.y += v.y; accA0.z += v.z; accA0.w += v.w;
        v = bf4_to_f4(make_uint2(p.z, p.w));
        accA1.x += v.x; accA1.y += v.y; accA1.z += v.z; accA1.w += v.w;
    }

    float4 s0, s1;
    s0.x = accA0.x + accB0.x; s0.y = accA0.y + accB0.y;
    s0.z = accA0.z + accB0.z; s0.w = accA0.w + accB0.w;
    s1.x = accA1.x + accB1.x; s1.y = accA1.y + accB1.y;
    s1.z = accA1.z + accB1.z; s1.w = accA1.w + accB1.w;
    s0.x += __shfl_xor_sync(0xFFFFFFFF, s0.x, 16);
    s0.y += __shfl_xor_sync(0xFFFFFFFF, s0.y, 16);
    s0.z += __shfl_xor_sync(0xFFFFFFFF, s0.z, 16);
    s0.w += __shfl_xor_sync(0xFFFFFFFF, s0.w, 16);
    s1.x += __shfl_xor_sync(0xFFFFFFFF, s1.x, 16);
    s1.y += __shfl_xor_sync(0xFFFFFFFF, s1.y, 16);
    s1.z += __shfl_xor_sync(0xFFFFFFFF, s1.z, 16);
    s1.w += __shfl_xor_sync(0xFFFFFFFF, s1.w, 16);

    float sc = 1.f / fmaxf((float)deg, 1.f);
    s0.x *= sc; s0.y *= sc; s0.z *= sc; s0.w *= sc;
    s1.x *= sc; s1.y *= sc; s1.z *= sc; s1.w *= sc;

    if (h == 0) {
        uint2 hi0, lo0, hi1, lo1;
        split4(s0, hi0, lo0);
        split4(s1, hi1, lo1);
        ((uint4*)(void*)g_agghi)[w * 16 + hl] = make_uint4(hi0.x, hi0.y, hi1.x, hi1.y);
        ((uint4*)(void*)g_agglo)[w * 16 + hl] = make_uint4(lo0.x, lo0.y, lo1.x, lo1.y);
    }
}

// ===================== HMMA bf16x3 transform (pipelined) ===================
__device__ __forceinline__ void prefetch_A(uint32_t sbase, int bufbase,
                                           int tile, int tid) {
    int row0 = tile * TILE_M;
    int op = tid & 63;
    int a2 = op >> 4;
    int u = op & 15;
    const char* arr;
    if (a2 == 0)      arr = (const char*)g_agghi;
    else if (a2 == 1) arr = (const char*)g_xhi;
    else if (a2 == 2) arr = (const char*)g_agglo;
    else              arr = (const char*)g_xlo;
    uint32_t dbase = sbase + bufbase + (a2 & 1) * 256 + (a2 >> 1) * ABUF_LO + u * 16;
    int rbase = tid >> 6;
#pragma unroll
    for (int i = 0; i < 8; i++) {
        int r = rbase + i * 4;
        int row = row0 + r;
        int ok = (row < N_NODES) ? 16 : 0;
        const char* src = arr + (long long)min(row, N_NODES - 1) * 256 + u * 16;
        CP16(dbase + r * LDAB, src, ok);
    }
}

__global__ void __launch_bounds__(256, 1)
transform_hmma(const float* __restrict__ W_l,
               const float* __restrict__ b_l,
               const float* __restrict__ W_r,
               float* __restrict__ out) {
    extern __shared__ char sm[];
    __shared__ float s_bias[128];

    int tid = threadIdx.x;
    int wid = tid >> 5;
    int lane = tid & 31;
    uint32_t sbase = smem_u32(sm);
    if (tid < 128) s_bias[tid] = b_l[tid];

    for (int idx = tid; idx < 128 * 64; idx += 256) {
        int n = idx >> 6;
        int kq = idx & 63;
        int k = kq * 4;
        const float* src = (k < 128) ? (W_l + n * 128 + k)
                                     : (W_r + n * 128 + (k - 128));
        float4 v = *(const float4*)src;
        uint2 hi, lo;
        split4(v, hi, lo);
        *(uint2*)(sm + OFF_BHI + n * LDAB + kq * 8) = hi;
        *(uint2*)(sm + OFF_BLO + n * LDAB + kq * 8) = lo;
    }

    int wr = (wid & 1) * 16;
    int nb = (wid >> 1) * 32;

    uint32_t aOff = (wr + (lane & 15)) * LDAB + ((lane >> 4) & 1) * 16;
    uint32_t bHi = sbase + OFF_BHI + (nb + (lane & 7)) * LDAB + ((lane >> 3) & 1) * 16;
    uint32_t bLo = bHi + (OFF_BLO - OFF_BHI);

    int tile = blockIdx.x;
    prefetch_A(sbase, 0, tile, tid);
    CP_COMMIT();

    int it = 0;
    for (; tile < NT2; tile += gridDim.x, it++) {
        int ntile = tile + gridDim.x;
        if (ntile < NT2) prefetch_A(sbase, ((it + 1) & 1) * ABUF_SZ, ntile, tid);
        CP_COMMIT();
        CP_WAIT1();
        __syncthreads();

        int row0 = tile * TILE_M;
        int g = lane >> 2;
        int tg = lane & 3;
        int r0 = row0 + wr + g;
        int r1 = r0 + 8;
        int c0 = g_cnt[r0];
        int c1 = g_cnt[r1];

        uint32_t abase = sbase + (it & 1) * ABUF_SZ;
        uint32_t aHi = abase + aOff;
        uint32_t aLo = aHi + ABUF_LO;

        float acc[4][4];
#pragma unroll
        for (int nt = 0; nt < 4; nt++)
#pragma unroll
            for (int j = 0; j < 4; j++) acc[nt][j] = 0.f;

#pragma unroll 2
        for (int ks = 0; ks < 16; ks++) {
            int kb = ks * 32;
            uint32_t a0, a1, a2, a3, l0, l1, l2, l3;
            LDSM4(a0, a1, a2, a3, aHi + kb);
            LDSM4(l0, l1, l2, l3, aLo + kb);
#pragma unroll
            for (int nt = 0; nt < 4; nt++) {
                uint32_t bh0, bh1, bl0, bl1;
                LDSM2(bh0, bh1, bHi + nt * 8 * LDAB + kb);
                LDSM2(bl0, bl1, bLo + nt * 8 * LDAB + kb);
                MMA16816(acc[nt], a0, a1, a2, a3, bh0, bh1);
                MMA16816(acc[nt], a0, a1, a2, a3, bl0, bl1);
                MMA16816(acc[nt], l0, l1, l2, l3, bh0, bh1);
            }
        }

        float df0 = (c0 > 0) ? 1.f : 0.f;
        float df1 = (c1 > 0) ? 1.f : 0.f;
#pragma unroll
        for (int nt = 0; nt < 4; nt++) {
            int col = nb + nt * 8 + tg * 2;
            float b0 = s_bias[col], b1 = s_bias[col + 1];
            float2 v0 = make_float2(acc[nt][0] + df0 * b0,
                                    acc[nt][1] + df0 * b1);
            *(float2*)(out + (long long)r0 * 128 + col) = v0;
            float2 v1 = make_float2(acc[nt][2] + df1 * b0,
                                    acc[nt][3] + df1 * b1);
            *(float2*)(out + (long long)r1 * 128 + col) = v1;
        }
        __syncthreads();
    }
}

// ---------------------------------------------------------------------------
// Launch
// ---------------------------------------------------------------------------
extern "C" void kernel_launch(void* const* d_in, const int* in_sizes, int n_in,
                              void* d_out, int out_size) {
    const float* x   = (const float*)d_in[0];
    const int*   ei  = (const int*)d_in[1];
    const float* W_l = (const float*)d_in[2];
    const float* b_l = (const float*)d_in[3];
    const float* W_r = (const float*)d_in[4];
    float*       out = (float*)d_out;
    int E = in_sizes[1] / 2;
    if (E > MAXE) E = MAXE;

    cudaFuncSetAttribute(transform_hmma,
                         cudaFuncAttributeMaxDynamicSharedMemorySize, SMEM_T);

    void* args[] = { (void*)&ei, (void*)&E, (void*)&x };
    cudaLaunchCooperativeKernel((void*)prep_kernel,
                                dim3(COOP_G), dim3(COOP_T), args, 0, 0);
    aggregate_kernel<<<(N_NODES * 32 + 255) / 256, 256>>>();
    transform_hmma<<<148, 256, SMEM_T>>>(W_l, b_l, W_r, out);
}

// round 15
// speedup vs baseline: 1.0143x; 1.0143x over previous
#include <cuda_runtime.h>
#include <cuda_bf16.h>
#include <cooperative_groups.h>
#include <cstdint>

namespace cg = cooperative_groups;

#define N_NODES 100000
#define F 128
#define MAXE 1600000

#define COOPA_G 592           // 4 blocks/SM, co-resident
#define SCAN_G 392            // 392*256 = 100352 >= N_NODES
#define SCAN_T 256

#define TILE_M 32
#define NT2 (N_NODES / TILE_M)                      // 3125 exact
#define LDAB 528
#define ABUF_LO 16896
#define ABUF_SZ 33792
#define OFF_BHI (2 * ABUF_SZ)
#define OFF_BLO (OFF_BHI + 128 * LDAB)
#define SMEM_T  (OFF_BLO + 128 * LDAB)              // 202752

// Scratch (allocation-free rule: __device__ globals)
__device__ int   g_cnt[N_NODES];
__device__ int   g_cur[N_NODES];
__device__ int   g_off[N_NODES];
__device__ int   g_bsum[512];
__device__ int   g_csr[MAXE];
__device__ uint2 g_agghi[N_NODES * 32];
__device__ uint2 g_agglo[N_NODES * 32];
__device__ uint2 g_xhi[N_NODES * 32];
__device__ uint2 g_xlo[N_NODES * 32];

// ---- bf16 rn split: hi = rn(v) (unbiased), lo = rn(v - float(hi)) ----
__device__ __forceinline__ uint32_t cvt2(float f0, float f1) {
    uint32_t d;
    asm("cvt.rn.bf16x2.f32 %0, %1, %2;" : "=r"(d) : "f"(f1), "f"(f0));
    return d;
}
__device__ __forceinline__ float4 bf4_to_f4(uint2 p) {
    float2 a = __bfloat1622float2(*(const __nv_bfloat162*)&p.x);
    float2 b = __bfloat1622float2(*(const __nv_bfloat162*)&p.y);
    return make_float4(a.x, a.y, b.x, b.y);
}
__device__ __forceinline__ void split4(float4 v, uint2& hi, uint2& lo) {
    hi.x = cvt2(v.x, v.y);
    hi.y = cvt2(v.z, v.w);
    float4 h = bf4_to_f4(hi);
    lo.x = cvt2(v.x - h.x, v.y - h.y);
    lo.y = cvt2(v.z - h.z, v.w - h.w);
}

#define MMA16816(c, a0, a1, a2, a3, b0, b1) \
    asm volatile("mma.sync.aligned.m16n8k16.row.col.f32.bf16.bf16.f32 " \
                 "{%0,%1,%2,%3}, {%4,%5,%6,%7}, {%8,%9}, {%0,%1,%2,%3};" \
                 : "+f"((c)[0]), "+f"((c)[1]), "+f"((c)[2]), "+f"((c)[3]) \
                 : "r"(a0), "r"(a1), "r"(a2), "r"(a3), "r"(b0), "r"(b1))
#define LDSM4(r0, r1, r2, r3, addr) \
    asm volatile("ldmatrix.sync.aligned.m8n8.x4.shared.b16 {%0,%1,%2,%3}, [%4];" \
                 : "=r"(r0), "=r"(r1), "=r"(r2), "=r"(r3) : "r"(addr))
#define CP16(dst, src, ssz) \
    asm volatile("cp.async.cg.shared.global [%0], [%1], 16, %2;" \
                 :: "r"(dst), "l"(src), "r"(ssz) : "memory")
#define CP_COMMIT() asm volatile("cp.async.commit_group;" ::: "memory")
#define CP_WAIT1()  asm volatile("cp.async.wait_group 1;" ::: "memory")

__device__ __forceinline__ uint32_t smem_u32(const void* p) {
    uint32_t a;
    asm("{ .reg .u64 t; cvta.to.shared.u64 t, %1; cvt.u32.u64 %0, t; }"
        : "=r"(a) : "l"(p));
    return a;
}

// ============ coopA: zero -> (xconv || hist) ================================
__global__ void __launch_bounds__(256, 4)
coopA_kernel(const int* __restrict__ ei, int E, const float* __restrict__ x) {
    cg::grid_group grid = cg::this_grid();
    int gid = blockIdx.x * 256 + threadIdx.x;
    int gstride = COOPA_G * 256;

    for (int i = gid; i < N_NODES; i += gstride) g_cnt[i] = 0;
    grid.sync();

    uint4* xhi4 = (uint4*)(void*)g_xhi;
    uint4* xlo4 = (uint4*)(void*)g_xlo;
    for (int i = gid; i < N_NODES * 16; i += gstride) {
        float4 v0 = ((const float4*)x)[i * 2];
        float4 v1 = ((const float4*)x)[i * 2 + 1];
        uint2 h0, l0, h1, l1;
        split4(v0, h0, l0);
        split4(v1, h1, l1);
        xhi4[i] = make_uint4(h0.x, h0.y, h1.x, h1.y);
        xlo4[i] = make_uint4(l0.x, l0.y, l1.x, l1.y);
    }
    int E4 = E >> 2;
    const int4* d4 = (const int4*)(ei + E);
    for (int e = gid; e < E4; e += gstride) {
        int4 d = d4[e];
        if ((unsigned)d.x < (unsigned)N_NODES) atomicAdd(&g_cnt[d.x], 1);
        if ((unsigned)d.y < (unsigned)N_NODES) atomicAdd(&g_cnt[d.y], 1);
        if ((unsigned)d.z < (unsigned)N_NODES) atomicAdd(&g_cnt[d.z], 1);
        if ((unsigned)d.w < (unsigned)N_NODES) atomicAdd(&g_cnt[d.w], 1);
    }
    for (int e = (E4 << 2) + gid; e < E; e += gstride) {
        int d = ei[E + e];
        if ((unsigned)d < (unsigned)N_NODES) atomicAdd(&g_cnt[d], 1);
    }
}

// ============ coop_scan: local block scan + self-computed base ==============
__global__ void __launch_bounds__(SCAN_T, 4)
coop_scan_kernel() {
    cg::grid_group grid = cg::this_grid();
    __shared__ int s[SCAN_T];
    int tid = threadIdx.x;
    int bid = blockIdx.x;
    int node = bid * SCAN_T + tid;

    int v = (node < N_NODES) ? g_cnt[node] : 0;
    s[tid] = v;
    __syncthreads();
#pragma unroll
    for (int d = 1; d < SCAN_T; d <<= 1) {
        int t = (tid >= d) ? s[tid - d] : 0;
        __syncthreads();
        s[tid] += t;
        __syncthreads();
    }
    int excl = s[tid] - v;
    if (tid == SCAN_T - 1) g_bsum[bid] = s[tid];
    grid.sync();

    int sum = 0;
    for (int i = tid; i < bid; i += SCAN_T) sum += g_bsum[i];
    __syncthreads();
    s[tid] = sum;
    __syncthreads();
#pragma unroll
    for (int d = SCAN_T / 2; d > 0; d >>= 1) {
        if (tid < d) s[tid] += s[tid + d];
        __syncthreads();
    }
    int base = s[0];
    if (node < N_NODES) {
        int off = excl + base;
        g_off[node] = off;
        g_cur[node] = off;
    }
}

// ============ fill ==========================================================
__global__ void fill_kernel(const int* __restrict__ ei, int E) {
    int idx = blockIdx.x * blockDim.x + threadIdx.x;
    int stride = gridDim.x * blockDim.x;
    int E4 = E >> 2;
    const int4* s4 = (const int4*)ei;
    const int4* d4 = (const int4*)(ei + E);
    for (int e = idx; e < E4; e += stride) {
        int4 s = s4[e];
        int4 d = d4[e];
        if ((unsigned)s.x < (unsigned)N_NODES && (unsigned)d.x < (unsigned)N_NODES)
            g_csr[atomicAdd(&g_cur[d.x], 1)] = s.x;
        if ((unsigned)s.y < (unsigned)N_NODES && (unsigned)d.y < (unsigned)N_NODES)
            g_csr[atomicAdd(&g_cur[d.y], 1)] = s.y;
        if ((unsigned)s.z < (unsigned)N_NODES && (unsigned)d.z < (unsigned)N_NODES)
            g_csr[atomicAdd(&g_cur[d.z], 1)] = s.z;
        if ((unsigned)s.w < (unsigned)N_NODES && (unsigned)d.w < (unsigned)N_NODES)
            g_csr[atomicAdd(&g_cur[d.w], 1)] = s.w;
    }
    for (int e = (E4 << 2) + idx; e < E; e += stride) {
        int s = ei[e];
        int d = ei[E + e];
        if ((unsigned)s < (unsigned)N_NODES && (unsigned)d < (unsigned)N_NODES)
            g_csr[atomicAdd(&g_cur[d], 1)] = s;
    }
}

// ---- aggregate: warp per node; paired-lane bf16 gather (LDG.128) ----------
__global__ void aggregate_kernel() {
    int gtid = blockIdx.x * blockDim.x + threadIdx.x;
    int w = gtid >> 5;
    int lane = gtid & 31;
    if (w >= N_NODES) return;
    int off = g_off[w];
    int deg = g_cnt[w];
    int end = off + deg;

    int h = lane >> 4;
    int hl = lane & 15;
    const uint4* xh4 = (const uint4*)(const void*)g_xhi;

    float4 accA0 = make_float4(0.f,0.f,0.f,0.f), accA1 = accA0;
    float4 accB0 = accA0, accB1 = accA0;

    int i = off;
    for (; i + 8 <= end; i += 8) {
        int e0 = g_csr[i + h];
        int e1 = g_csr[i + 2 + h];
        int e2 = g_csr[i + 4 + h];
        int e3 = g_csr[i + 6 + h];
        uint4 p0 = xh4[e0 * 16 + hl];
        uint4 p1 = xh4[e1 * 16 + hl];
        uint4 p2 = xh4[e2 * 16 + hl];
        uint4 p3 = xh4[e3 * 16 + hl];
        float4 v;
        v = bf4_to_f4(make_uint2(p0.x, p0.y));
        accA0.x += v.x; accA0.y += v.y; accA0.z += v.z; accA0.w += v.w;
        v = bf4_to_f4(make_uint2(p0.z, p0.w));
        accA1.x += v.x; accA1.y += v.y; accA1.z += v.z; accA1.w += v.w;
        v = bf4_to_f4(make_uint2(p1.x, p1.y));
        accB0.x += v.x; accB0.y += v.y; accB0.z += v.z; accB0.w += v.w;
        v = bf4_to_f4(make_uint2(p1.z, p1.w));
        accB1.x += v.x; accB1.y += v.y; accB1.z += v.z; accB1.w += v.w;
        v = bf4_to_f4(make_uint2(p2.x, p2.y));
        accA0.x += v.x; accA0.y += v.y; accA0.z += v.z; accA0.w += v.w;
        v = bf4_to_f4(make_uint2(p2.z, p2.w));
        accA1.x += v.x; accA1.y += v.y; accA1.z += v.z; accA1.w += v.w;
        v = bf4_to_f4(make_uint2(p3.x, p3.y));
        accB0.x += v.x; accB0.y += v.y; accB0.z += v.z; accB0.w += v.w;
        v = bf4_to_f4(make_uint2(p3.z, p3.w));
        accB1.x += v.x; accB1.y += v.y; accB1.z += v.z; accB1.w += v.w;
    }
    for (; i + 2 <= end; i += 2) {
        int e = g_csr[i + h];
        uint4 p = xh4[e * 16 + hl];
        float4 v = bf4_to_f4(make_uint2(p.x, p.y));
        accA0.x += v.x; accA0.y += v.y; accA0.z += v.z; accA0.w += v.w;
        v = bf4_to_f4(make_uint2(p.z, p.w));
        accA1.x += v.x; accA1.y += v.y; accA1.z += v.z; accA1.w += v.w;
    }
    if (i < end && h == 0) {
        int e = g_csr[i];
        uint4 p = xh4[e * 16 + hl];
        float4 v = bf4_to_f4(make_uint2(p.x, p.y));
        accA0.x += v.x; accA0.y += v.y; accA0.z += v.z; accA0.w += v.w;
        v = bf4_to_f4(make_uint2(p.z, p.w));
        accA1.x += v.x; accA1.y += v.y; accA1.z += v.z; accA1.w += v.w;
    }

    float4 s0, s1;
    s0.x = accA0.x + accB0.x; s0.y = accA0.y + accB0.y;
    s0.z = accA0.z + accB0.z; s0.w = accA0.w + accB0.w;
    s1.x = accA1.x + accB1.x; s1.y = accA1.y + accB1.y;
    s1.z = accA1.z + accB1.z; s1.w = accA1.w + accB1.w;
    s0.x += __shfl_xor_sync(0xFFFFFFFF, s0.x, 16);
    s0.y += __shfl_xor_sync(0xFFFFFFFF, s0.y, 16);
    s0.z += __shfl_xor_sync(0xFFFFFFFF, s0.z, 16);
    s0.w += __shfl_xor_sync(0xFFFFFFFF, s0.w, 16);
    s1.x += __shfl_xor_sync(0xFFFFFFFF, s1.x, 16);
    s1.y += __shfl_xor_sync(0xFFFFFFFF, s1.y, 16);
    s1.z += __shfl_xor_sync(0xFFFFFFFF, s1.z, 16);
    s1.w += __shfl_xor_sync(0xFFFFFFFF, s1.w, 16);

    float sc = 1.f / fmaxf((float)deg, 1.f);
    s0.x *= sc; s0.y *= sc; s0.z *= sc; s0.w *= sc;
    s1.x *= sc; s1.y *= sc; s1.z *= sc; s1.w *= sc;

    if (h == 0) {
        uint2 hi0, lo0, hi1, lo1;
        split4(s0, hi0, lo0);
        split4(s1, hi1, lo1);
        ((uint4*)(void*)g_agghi)[w * 16 + hl] = make_uint4(hi0.x, hi0.y, hi1.x, hi1.y);
        ((uint4*)(void*)g_agglo)[w * 16 + hl] = make_uint4(lo0.x, lo0.y, lo1.x, lo1.y);
    }
}

// ===================== HMMA bf16x3 transform (pipelined, LDSM4-B) ==========
__device__ __forceinline__ void prefetch_A(uint32_t sbase, int bufbase,
                                           int tile, int tid) {
    int row0 = tile * TILE_M;
    int op = tid & 63;
    int a2 = op >> 4;
    int u = op & 15;
    const char* arr;
    if (a2 == 0)      arr = (const char*)g_agghi;
    else if (a2 == 1) arr = (const char*)g_xhi;
    else if (a2 == 2) arr = (const char*)g_agglo;
    else              arr = (const char*)g_xlo;
    uint32_t dbase = sbase + bufbase + (a2 & 1) * 256 + (a2 >> 1) * ABUF_LO + u * 16;
    int rbase = tid >> 6;
#pragma unroll
    for (int i = 0; i < 8; i++) {
        int r = rbase + i * 4;
        int row = row0 + r;
        int ok = (row < N_NODES) ? 16 : 0;
        const char* src = arr + (long long)min(row, N_NODES - 1) * 256 + u * 16;
        CP16(dbase + r * LDAB, src, ok);
    }
}

__global__ void __launch_bounds__(256, 1)
transform_hmma(const float* __restrict__ W_l,
               const float* __restrict__ b_l,
               const float* __restrict__ W_r,
               float* __restrict__ out) {
    extern __shared__ char sm[];
    __shared__ float s_bias[128];

    int tid = threadIdx.x;
    int wid = tid >> 5;
    int lane = tid & 31;
    uint32_t sbase = smem_u32(sm);
    if (tid < 128) s_bias[tid] = b_l[tid];

    for (int idx = tid; idx < 128 * 64; idx += 256) {
        int n = idx >> 6;
        int kq = idx & 63;
        int k = kq * 4;
        const float* src = (k < 128) ? (W_l + n * 128 + k)
                                     : (W_r + n * 128 + (k - 128));
        float4 v = *(const float4*)src;
        uint2 hi, lo;
        split4(v, hi, lo);
        *(uint2*)(sm + OFF_BHI + n * LDAB + kq * 8) = hi;
        *(uint2*)(sm + OFF_BLO + n * LDAB + kq * 8) = lo;
    }

    int wr = (wid & 1) * 16;
    int nb = (wid >> 1) * 32;

    uint32_t aOff = (wr + (lane & 15)) * LDAB + ((lane >> 4) & 1) * 16;
    // B x4 lane map: rows nb + (lane&7) + ((lane>>4)*8), k-half (lane>>3)&1
    uint32_t bRow = nb + (lane & 7) + ((lane >> 4) << 3);
    uint32_t bHiP = sbase + OFF_BHI + bRow * LDAB + ((lane >> 3) & 1) * 16;
    uint32_t bLoP = bHiP + (OFF_BLO - OFF_BHI);

    int tile = blockIdx.x;
    prefetch_A(sbase, 0, tile, tid);
    CP_COMMIT();

    int it = 0;
    for (; tile < NT2; tile += gridDim.x, it++) {
        int ntile = tile + gridDim.x;
        if (ntile < NT2) prefetch_A(sbase, ((it + 1) & 1) * ABUF_SZ, ntile, tid);
        CP_COMMIT();
        CP_WAIT1();
        __syncthreads();

        int row0 = tile * TILE_M;
        int g = lane >> 2;
        int tg = lane & 3;
        int r0 = row0 + wr + g;
        int r1 = r0 + 8;
        int c0 = g_cnt[r0];
        int c1 = g_cnt[r1];

        uint32_t abase = sbase + (it & 1) * ABUF_SZ;
        uint32_t aHi = abase + aOff;
        uint32_t aLo = aHi + ABUF_LO;

        float acc[4][4];
#pragma unroll
        for (int nt = 0; nt < 4; nt++)
#pragma unroll
            for (int j = 0; j < 4; j++) acc[nt][j] = 0.f;

#pragma unroll 2
        for (int ks = 0; ks < 16; ks++) {
            int kb = ks * 32;
            uint32_t a0, a1, a2, a3, l0, l1, l2, l3;
            LDSM4(a0, a1, a2, a3, aHi + kb);
            LDSM4(l0, l1, l2, l3, aLo + kb);
#pragma unroll
            for (int ntp = 0; ntp < 2; ntp++) {
                uint32_t bh0, bh1, bh2, bh3, bl0, bl1, bl2, bl3;
                LDSM4(bh0, bh1, bh2, bh3, bHiP + ntp * 16 * LDAB + kb);
                LDSM4(bl0, bl1, bl2, bl3, bLoP + ntp * 16 * LDAB + kb);
                MMA16816(acc[2*ntp+0], a0, a1, a2, a3, bh0, bh1);
                MMA16816(acc[2*ntp+0], a0, a1, a2, a3, bl0, bl1);
                MMA16816(acc[2*ntp+0], l0, l1, l2, l3, bh0, bh1);
                MMA16816(acc[2*ntp+1], a0, a1, a2, a3, bh2, bh3);
                MMA16816(acc[2*ntp+1], a0, a1, a2, a3, bl2, bl3);
                MMA16816(acc[2*ntp+1], l0, l1, l2, l3, bh2, bh3);
            }
        }

        float df0 = (c0 > 0) ? 1.f : 0.f;
        float df1 = (c1 > 0) ? 1.f : 0.f;
#pragma unroll
        for (int nt = 0; nt < 4; nt++) {
            int col = nb + nt * 8 + tg * 2;
            float b0 = s_bias[col], b1 = s_bias[col + 1];
            float2 v0 = make_float2(acc[nt][0] + df0 * b0,
                                    acc[nt][1] + df0 * b1);
            *(float2*)(out + (long long)r0 * 128 + col) = v0;
            float2 v1 = make_float2(acc[nt][2] + df1 * b0,
                                    acc[nt][3] + df1 * b1);
            *(float2*)(out + (long long)r1 * 128 + col) = v1;
        }
        __syncthreads();
    }
}

// ---------------------------------------------------------------------------
// Launch
// ---------------------------------------------------------------------------
extern "C" void kernel_launch(void* const* d_in, const int* in_sizes, int n_in,
                              void* d_out, int out_size) {
    const float* x   = (const float*)d_in[0];
    const int*   ei  = (const int*)d_in[1];
    const float* W_l = (const float*)d_in[2];
    const float* b_l = (const float*)d_in[3];
    const float* W_r = (const float*)d_in[4];
    float*       out = (float*)d_out;
    int E = in_sizes[1] / 2;
    if (E > MAXE) E = MAXE;

    cudaFuncSetAttribute(transform_hmma,
                         cudaFuncAttributeMaxDynamicSharedMemorySize, SMEM_T);

    void* argsA[] = { (void*)&ei, (void*)&E, (void*)&x };
    cudaLaunchCooperativeKernel((void*)coopA_kernel,
                                dim3(COOPA_G), dim3(256), argsA, 0, 0);
    cudaLaunchCooperativeKernel((void*)coop_scan_kernel,
                                dim3(SCAN_G), dim3(SCAN_T), nullptr, 0, 0);
    fill_kernel<<<2048, 256>>>(ei, E);
    aggregate_kernel<<<(N_NODES * 32 + 255) / 256, 256>>>();
    transform_hmma<<<148, 256, SMEM_T>>>(W_l, b_l, W_r, out);
}